// round 12
// baseline (speedup 1.0000x reference)
#include <cuda_runtime.h>
#include <cstdint>

#define NTOK 16384
#define DIN 64
#define DOUT 64
#define NC 512
#define KSEL 16
#define NASSIGN (NTOK*KSEL)
#define NDS 516          // padded ds row stride (floats)
#define NXD 130          // padded duplicated-x row stride (floats)

typedef unsigned long long u64;
typedef unsigned int u32;

// ---------------- scratch (device globals: no allocation allowed) -------------
__device__ float g_ctrT[DIN*NC];        // centers transposed [k][c]
__device__ float g_scores[NASSIGN];     // softmax scores per (token, j)
__device__ int   g_idx[NASSIGN];        // selected center per (token, j)
__device__ int   g_cnt[NC];
__device__ int   g_off[NC];
__device__ int   g_cursor[NC];
__device__ int   g_tok[NASSIGN];        // bucket -> token id
__device__ float g_ascore[NASSIGN];     // bucket -> score
__device__ int   g_dslot[NASSIGN];      // bucket -> (token*16+j) destination slot
__device__ float g_part[(size_t)NASSIGN*DOUT]; // 67 MB partials, slot-addressed
__device__ float g_c2[NC];              // ||c||^2 + 3072 bias
__device__ int   g_tiles[8192];         // (center, rowStart) pairs
__device__ int   g_ntiles;
__device__ int   g_work;                // dynamic tile cursor for k_gemm
__device__ int   g_flag;                // scan-done flag for k_ss

// ---------------- packed f32x2 helpers ----------------------------------------
__device__ __forceinline__ u64 dupf(float x){
    u64 r; asm("mov.b64 %0, {%1, %1};" : "=l"(r) : "f"(x)); return r;
}
__device__ __forceinline__ void ffma2(u64 &d, u64 a, u64 b){
    asm("fma.rn.f32x2 %0, %1, %2, %0;" : "+l"(d) : "l"(a), "l"(b));
}
__device__ __forceinline__ u64 ffma2v(u64 a, u64 b, u64 c){
    u64 d; asm("fma.rn.f32x2 %0, %1, %2, %3;" : "=l"(d) : "l"(a), "l"(b), "l"(c)); return d;
}
__device__ __forceinline__ u64 fadd2(u64 a, u64 b){
    u64 r; asm("add.rn.f32x2 %0, %1, %2;" : "=l"(r) : "l"(a), "l"(b)); return r;
}
__device__ __forceinline__ u64 fmul2(u64 a, u64 b){
    u64 r; asm("mul.rn.f32x2 %0, %1, %2;" : "=l"(r) : "l"(a), "l"(b)); return r;
}

// bitonic sort of 16 u32 ascending: every CAS = 2 IMNMX.
#define BITONIC16U(P) do{ \
    _Pragma("unroll") \
    for(int k_=2;k_<=16;k_<<=1){ \
        _Pragma("unroll") \
        for(int j_=k_>>1;j_>0;j_>>=1){ \
            _Pragma("unroll") \
            for(int i_=0;i_<16;i_++){ \
                int l_=i_^j_; \
                if(l_>i_){ \
                    u32 a_=P[i_], b_=P[l_]; \
                    u32 lo_ = a_<b_?a_:b_, hi_ = a_<b_?b_:a_; \
                    if((i_&k_)==0){ P[i_]=lo_; P[l_]=hi_; } \
                    else          { P[i_]=hi_; P[l_]=lo_; } \
                } \
            } \
        } \
    } }while(0)

// ---------------- K0a: transpose centers ---------------------------------------
__global__ void k_prep_t(const float* __restrict__ ctrs){
    int e = blockIdx.x*256 + threadIdx.x;   // 32768 elements
    int k = e >> 9, c = e & 511;
    g_ctrT[k*NC + c] = ctrs[c*DIN + k];
}

// ---------------- K0b: c2 (+bias) ----------------------------------------------
// bias 3072 keeps every key inside the [2048,4096) binade -> mantissa bits give
// the exact order -> u32 packed selection. Bias cancels in softmax.
__global__ void k_prep_c(const float* __restrict__ ctrs){
    int c = blockIdx.x*256 + threadIdx.x;   // 512 centers
    const float4* c4 = (const float4*)ctrs;
    float s = 3072.0f;
    #pragma unroll
    for(int seg=0; seg<16; seg++){
        float4 v = c4[c*16 + seg];
        s += v.x*v.x + v.y*v.y + v.z*v.z + v.w*v.w;
    }
    g_c2[c] = s;
}

// ---------------- K0c: zero counters -------------------------------------------
__global__ void k_prep_z(){
    int c = blockIdx.x*256 + threadIdx.x;
    g_cnt[c] = 0;
    if(c == 0){ g_work = 0; g_flag = 0; }
}

// ---------------- per-token branchless top-16 + softmax (u32 packed) -----------
__device__ __forceinline__ void select16(const float* ds, int t, int lane,
                                         int gt){
    u32 P[16];
    #pragma unroll
    for(int i=0;i<16;i++){
        float v = ds[t*NDS + lane + 32*i];
        P[i] = (__float_as_uint(v) << 9) | (u32)(i*32 + lane);
    }
    BITONIC16U(P);

    u32 sel = 0;
    #pragma unroll
    for(int j=0;j<16;j++){
        u32 m = __reduce_min_sync(0xffffffffu, P[0]);
        if(lane == j) sel = m;
        bool take = (P[0] == m);      // packed values unique -> exactly one lane
        #pragma unroll
        for(int i=0;i<15;i++) P[i] = take ? P[i+1] : P[i];
        P[15] = take ? 0xFFFFFFFFu : P[15];
    }

    if(lane < 16){
        u32 c = sel & 511u;
        float d = __uint_as_float(0x45000000u | (sel >> 9));  // exact key
        float m0 = __shfl_sync(0x0000ffffu, d, 0);
        float e = expf(m0 - d);
        float s = e;
        #pragma unroll
        for(int o=8;o>=1;o>>=1) s += __shfl_xor_sync(0x0000ffffu, s, o);
        g_scores[gt*16 + lane] = e / s;
        g_idx[gt*16 + lane]    = (int)c;
        atomicAdd(&g_cnt[c], 1);
    }
}

// ---------------- K1: fused distance GEMM + branchless top-16 + softmax --------
// persistent: 148 blocks x 512 thr, tile = 32 tokens x 512 centers.
// x tile stored PRE-DUPLICATED (xsd[r][2k]=(x,x)) -> FFMA2 'a' operand is one
// LDS.64 (broadcast, conflict-free); no mov.b64 duplication in the hot loop.
// thread tile: 4 tokens x 8 centers.  warp = 16 tokens x 64 centers.
__global__ __launch_bounds__(512,1) void k_fused(const float* __restrict__ x){
    extern __shared__ char smraw[];
    float* xsd = (float*)smraw;            // 32*130 duplicated x (16.6KB)
    float* ds  = xsd + 32*NXD;             // 32*516 distance keys  (64.5KB)

    int tid = threadIdx.x;
    int w  = tid >> 5, lane = tid & 31;
    int og = lane & 7, tg = lane >> 3;     // tg in 0..3
    int cb = (w & 7)*64 + og*8;            // this thread's 8 centers
    int tb = (w >> 3)*16;                  // warp token base (0 or 16)
    const float4* x4 = (const float4*)x;

    for(int tile = blockIdx.x; tile < 512; tile += 148){
        int ttile = tile*32;
        __syncthreads();                   // prev selection reads done
        {   // fill duplicated x tile: one float4 per thread -> 4 (v,v) pairs
            int rr = tid >> 4, seg = tid & 15;
            float4 v = x4[(ttile+rr)*16 + seg];
            float2* d = (float2*)&xsd[rr*NXD + seg*8];
            d[0] = make_float2(v.x, v.x);
            d[1] = make_float2(v.y, v.y);
            d[2] = make_float2(v.z, v.z);
            d[3] = make_float2(v.w, v.w);
        }
        __syncthreads();

        u64 acc[4][4];
        #pragma unroll
        for(int i=0;i<4;i++){ acc[i][0]=0; acc[i][1]=0; acc[i][2]=0; acc[i][3]=0; }

        #pragma unroll 8
        for(int k=0;k<64;k++){
            ulonglong2 p0 = *(const ulonglong2*)&g_ctrT[k*NC + cb];
            ulonglong2 p1 = *(const ulonglong2*)&g_ctrT[k*NC + cb + 4];
            #pragma unroll
            for(int i=0;i<4;i++){
                u64 xv = *(const u64*)&xsd[(tb + tg + 4*i)*NXD + 2*k];
                ffma2(acc[i][0], xv, p0.x);
                ffma2(acc[i][1], xv, p0.y);
                ffma2(acc[i][2], xv, p1.x);
                ffma2(acc[i][3], xv, p1.y);
            }
        }
        // key = c2b - 2*(x.c), write to ds
        {
            ulonglong2 q0 = *(const ulonglong2*)&g_c2[cb];
            ulonglong2 q1 = *(const ulonglong2*)&g_c2[cb + 4];
            u64 m2 = dupf(-2.0f);
            #pragma unroll
            for(int i=0;i<4;i++){
                int r = tb + tg + 4*i;
                *(ulonglong2*)&ds[r*NDS + cb] =
                    make_ulonglong2(ffma2v(acc[i][0], m2, q0.x),
                                    ffma2v(acc[i][1], m2, q0.y));
                *(ulonglong2*)&ds[r*NDS + cb + 4] =
                    make_ulonglong2(ffma2v(acc[i][2], m2, q1.x),
                                    ffma2v(acc[i][3], m2, q1.y));
            }
        }
        __syncthreads();

        // selection: warp w handles tokens 2w, 2w+1
        select16(ds, w*2,     lane, ttile + w*2);
        select16(ds, w*2 + 1, lane, ttile + w*2 + 1);
    }
}

// ---------------- K2: fused scan (block 0) + scatter (all 512 blocks) ----------
__global__ __launch_bounds__(512) void k_ss(){
    __shared__ int wsum[16];
    int tid = threadIdx.x;

    if(blockIdx.x == 0){
        int c = tid, lane = c & 31, w = c >> 5;
        int cn = g_cnt[c];
        int s = cn;
        #pragma unroll
        for(int o=1;o<32;o<<=1){ int v=__shfl_up_sync(0xffffffffu,s,o); if(lane>=o) s+=v; }
        if(lane==31) wsum[w] = s;
        __syncthreads();
        if(w==0){
            int t = (lane<16) ? wsum[lane] : 0;
            #pragma unroll
            for(int o=1;o<16;o<<=1){ int v=__shfl_up_sync(0xffffffffu,t,o); if(lane>=o) t+=v; }
            if(lane<16) wsum[lane] = t;
        }
        __syncthreads();
        int inc = s + ((w>0) ? wsum[w-1] : 0);
        g_off[c] = inc - cn;
        g_cursor[c] = inc - cn;

        int t = (cn + 127) >> 7;
        __syncthreads();
        int s2 = t;
        #pragma unroll
        for(int o=1;o<32;o<<=1){ int v=__shfl_up_sync(0xffffffffu,s2,o); if(lane>=o) s2+=v; }
        if(lane==31) wsum[w] = s2;
        __syncthreads();
        if(w==0){
            int tt = (lane<16) ? wsum[lane] : 0;
            #pragma unroll
            for(int o=1;o<16;o<<=1){ int v=__shfl_up_sync(0xffffffffu,tt,o); if(lane>=o) tt+=v; }
            if(lane<16) wsum[lane] = tt;
        }
        __syncthreads();
        int tinc = s2 + ((w>0) ? wsum[w-1] : 0);
        int tb = tinc - t;
        for(int i=0;i<t;i++){
            g_tiles[2*(tb+i)]   = c;
            g_tiles[2*(tb+i)+1] = i << 7;
        }
        if(c == 511) g_ntiles = tinc;
        __threadfence();
        __syncthreads();
        if(tid == 0) *((volatile int*)&g_flag) = 1;
    } else {
        if(tid == 0){ while(*((volatile int*)&g_flag) == 0){ } }
        __syncthreads();
    }

    int a = blockIdx.x*512 + tid;          // (token<<4)|j
    int c = g_idx[a];
    float s = g_scores[a];
    int pos = atomicAdd(&g_cursor[c], 1);
    g_tok[pos]   = a >> 4;
    g_ascore[pos]= s;
    g_dslot[pos] = a;
}

// ---------------- K3: grouped GEMM per (center, 128-row tile) ------------------
// 256 thr, thread tile 4 rows x 8 cols (split og*4 / og*4+32).
// Warp w owns rows [16w, 16w+16): whole-warp skip when 16w >= m.
__global__ __launch_bounds__(256,3) void k_gemm(const float* __restrict__ x,
                                                const float* __restrict__ Wv,
                                                const float* __restrict__ Ov){
    __shared__ float ws[DIN*DOUT];   // ws[k*64 + p] (row-major copy of Wv[c])
    __shared__ float xs[128*DIN];    // xs[r*64 + (k ^ 8*((r>>2)&3))]
    __shared__ int s_tile;
    int nt = g_ntiles;
    int tid = threadIdx.x;
    int og = tid & 7, tg = tid >> 3;     // tg 0..31
    int w  = tid >> 5;
    int xsw = (tg & 3) * 8;              // rows tg*4..tg*4+3 share (r>>2)&3 == tg&3
    const float4* x4 = (const float4*)x;

    while(true){
        __syncthreads();             // smem reuse + s_tile protection
        if(tid == 0) s_tile = atomicAdd(&g_work, 1);
        __syncthreads();
        int tile = s_tile;
        if(tile >= nt) break;

        int c      = g_tiles[2*tile];
        int rstart = g_tiles[2*tile+1];
        int base   = g_off[c] + rstart;
        int m      = g_cnt[c] - rstart; if(m > 128) m = 128;

        const float4* wv4 = (const float4*)(Wv + (size_t)c*4096);
        float4* ws4 = (float4*)ws;
        #pragma unroll
        for(int f=0; f<4; f++) ws4[tid + 256*f] = wv4[tid + 256*f];

        #pragma unroll
        for(int it=0; it<8; it++){
            int idx2 = tid + 256*it;
            int rr = idx2 >> 4, seg = idx2 & 15;
            if(rr < m){
                float4 v = x4[g_tok[base+rr]*16 + seg];
                *(float4*)&xs[rr*64 + ((seg*4) ^ (((rr>>2)&3)*8))] = v;
            }
        }
        __syncthreads();

        if(16*w < m){                   // warp-uniform: skip padded rows
            u64 acc[4][4];
            #pragma unroll
            for(int i=0;i<4;i++){ acc[i][0]=0; acc[i][1]=0; acc[i][2]=0; acc[i][3]=0; }

            #pragma unroll 4
            for(int k4=0;k4<16;k4++){
                float v4[4][4];
                #pragma unroll
                for(int i=0;i<4;i++)
                    *(float4*)v4[i] = *(const float4*)&xs[(tg*4+i)*64 + ((k4*4) ^ xsw)];
                #pragma unroll
                for(int kk=0;kk<4;kk++){
                    int k = k4*4 + kk;
                    ulonglong2 p0 = *(const ulonglong2*)&ws[k*64 + og*4];
                    ulonglong2 p1 = *(const ulonglong2*)&ws[k*64 + og*4 + 32];
                    #pragma unroll
                    for(int i=0;i<4;i++){
                        u64 xv = dupf(v4[i][kk]);
                        ffma2(acc[i][0], xv, p0.x);
                        ffma2(acc[i][1], xv, p0.y);
                        ffma2(acc[i][2], xv, p1.x);
                        ffma2(acc[i][3], xv, p1.y);
                    }
                }
            }
            ulonglong2 q0 = *(const ulonglong2*)&Ov[(size_t)c*64 + og*4];
            ulonglong2 q1 = *(const ulonglong2*)&Ov[(size_t)c*64 + og*4 + 32];
            #pragma unroll
            for(int i=0;i<4;i++){
                int r = tg*4 + i;
                if(r < m){
                    int slot = g_dslot[base + r];
                    u64 sv = dupf(g_ascore[base + r]);
                    ulonglong2* d0 = (ulonglong2*)&g_part[(size_t)slot*64 + og*4];
                    ulonglong2* d1 = (ulonglong2*)&g_part[(size_t)slot*64 + og*4 + 32];
                    *d0 = make_ulonglong2(fmul2(fadd2(acc[i][0], q0.x), sv),
                                          fmul2(fadd2(acc[i][1], q0.y), sv));
                    *d1 = make_ulonglong2(fmul2(fadd2(acc[i][2], q1.x), sv),
                                          fmul2(fadd2(acc[i][3], q1.y), sv));
                }
            }
        }
    }
}

// ---------------- K4: streamed reduce of 16 contiguous partials per token ------
__global__ __launch_bounds__(256) void k_reduce(float* __restrict__ out){
    int t  = blockIdx.x*16 + (threadIdx.x >> 4);
    int c4 = threadIdx.x & 15;
    const float4* p = (const float4*)(g_part + (size_t)t*16*64) + c4;
    float4 acc = make_float4(0.f,0.f,0.f,0.f);
    #pragma unroll
    for(int j=0;j<16;j++){
        float4 v = p[j*16];
        acc.x += v.x; acc.y += v.y; acc.z += v.z; acc.w += v.w;
    }
    ((float4*)out)[t*16 + c4] = acc;
}

// ---------------- launch -------------------------------------------------------
extern "C" void kernel_launch(void* const* d_in, const int* in_sizes, int n_in,
                              void* d_out, int out_size){
    const float* x    = (const float*)d_in[0];
    const float* ctrs = (const float*)d_in[1];
    const float* Wv   = (const float*)d_in[2];
    const float* Ov   = (const float*)d_in[3];
    float* out = (float*)d_out;

    const int FUSED_SMEM = (32*NXD + 32*NDS)*4;   // ~81 KB
    cudaFuncSetAttribute(k_fused, cudaFuncAttributeMaxDynamicSharedMemorySize,
                         FUSED_SMEM);

    k_prep_t<<<128, 256>>>(ctrs);
    k_prep_c<<<2, 256>>>(ctrs);
    k_prep_z<<<2, 256>>>();
    k_fused <<<148, 512, FUSED_SMEM>>>(x);   // launch #4 -> ncu capture target
    k_ss    <<<512, 512>>>();
    k_gemm  <<<444, 256>>>(x, Wv, Ov);
    k_reduce<<<1024, 256>>>(out);
}

// round 13
// speedup vs baseline: 1.0233x; 1.0233x over previous
#include <cuda_runtime.h>
#include <cstdint>

#define NTOK 16384
#define DIN 64
#define DOUT 64
#define NC 512
#define KSEL 16
#define NASSIGN (NTOK*KSEL)
#define NXP 130          // xp pair-row stride (floats): 520B, 65*8 -> u64-aligned

typedef unsigned long long u64;
typedef unsigned int u32;

// ---------------- scratch (device globals: no allocation allowed) -------------
__device__ float g_ctrT[DIN*NC];        // centers transposed [k][c]
__device__ float g_scores[NASSIGN];     // softmax scores per (token, j)
__device__ int   g_idx[NASSIGN];        // selected center per (token, j)
__device__ int   g_cnt[NC];
__device__ int   g_off[NC];
__device__ int   g_cursor[NC];
__device__ int   g_tok[NASSIGN];        // bucket -> token id
__device__ float g_ascore[NASSIGN];     // bucket -> score
__device__ int   g_dslot[NASSIGN];      // bucket -> (token*16+j) destination slot
__device__ float g_part[(size_t)NASSIGN*DOUT]; // 67 MB partials, slot-addressed
__device__ float g_c2[NC];              // ||c||^2 + 3072 bias
__device__ int   g_tiles[8192];         // (center, rowStart) pairs
__device__ int   g_ntiles;
__device__ int   g_work;                // dynamic tile cursor for k_gemm
__device__ int   g_flag;                // scan-done flag for k_ss

// ---------------- packed f32x2 helpers ----------------------------------------
__device__ __forceinline__ u64 dupf(float x){
    u64 r; asm("mov.b64 %0, {%1, %1};" : "=l"(r) : "f"(x)); return r;
}
__device__ __forceinline__ u64 pk(float a, float b){
    u64 r; asm("mov.b64 %0, {%1, %2};" : "=l"(r) : "f"(a), "f"(b)); return r;
}
__device__ __forceinline__ void ffma2(u64 &d, u64 a, u64 b){
    asm("fma.rn.f32x2 %0, %1, %2, %0;" : "+l"(d) : "l"(a), "l"(b));
}
__device__ __forceinline__ u64 ffma2v(u64 a, u64 b, u64 c){
    u64 d; asm("fma.rn.f32x2 %0, %1, %2, %3;" : "=l"(d) : "l"(a), "l"(b), "l"(c)); return d;
}
__device__ __forceinline__ u64 fadd2(u64 a, u64 b){
    u64 r; asm("add.rn.f32x2 %0, %1, %2;" : "=l"(r) : "l"(a), "l"(b)); return r;
}
__device__ __forceinline__ u64 fmul2(u64 a, u64 b){
    u64 r; asm("mul.rn.f32x2 %0, %1, %2;" : "=l"(r) : "l"(a), "l"(b)); return r;
}
__device__ __forceinline__ float lo2(u64 v){ float2 f = *(float2*)&v; return f.x; }
__device__ __forceinline__ float hi2(u64 v){ float2 f = *(float2*)&v; return f.y; }

// bitonic sort of 16 u32 ascending: every CAS = 2 IMNMX.
#define BITONIC16U(P) do{ \
    _Pragma("unroll") \
    for(int k_=2;k_<=16;k_<<=1){ \
        _Pragma("unroll") \
        for(int j_=k_>>1;j_>0;j_>>=1){ \
            _Pragma("unroll") \
            for(int i_=0;i_<16;i_++){ \
                int l_=i_^j_; \
                if(l_>i_){ \
                    u32 a_=P[i_], b_=P[l_]; \
                    u32 lo_ = a_<b_?a_:b_, hi_ = a_<b_?b_:a_; \
                    if((i_&k_)==0){ P[i_]=lo_; P[l_]=hi_; } \
                    else          { P[i_]=hi_; P[l_]=lo_; } \
                } \
            } \
        } \
    } }while(0)

// ---------------- K0a: transpose centers ---------------------------------------
__global__ void k_prep_t(const float* __restrict__ ctrs){
    int e = blockIdx.x*256 + threadIdx.x;   // 32768 elements
    int k = e >> 9, c = e & 511;
    g_ctrT[k*NC + c] = ctrs[c*DIN + k];
}

// ---------------- K0b: c2 (+bias) ----------------------------------------------
// bias 3072 keeps every key inside the [2048,4096) binade -> mantissa bits give
// the exact order -> u32 packed selection. Bias cancels in softmax.
__global__ void k_prep_c(const float* __restrict__ ctrs){
    int c = blockIdx.x*256 + threadIdx.x;   // 512 centers
    const float4* c4 = (const float4*)ctrs;
    float s = 3072.0f;
    #pragma unroll
    for(int seg=0; seg<16; seg++){
        float4 v = c4[c*16 + seg];
        s += v.x*v.x + v.y*v.y + v.z*v.z + v.w*v.w;
    }
    g_c2[c] = s;
}

// ---------------- K0c: zero counters -------------------------------------------
__global__ void k_prep_z(){
    int c = blockIdx.x*256 + threadIdx.x;
    g_cnt[c] = 0;
    if(c == 0){ g_work = 0; g_flag = 0; }
}

// ---------------- per-token branchless top-16 + softmax (u32 packed) -----------
__device__ __forceinline__ void select16(const float* ds, int t, int lane,
                                         int gt){
    u32 P[16];
    #pragma unroll
    for(int i=0;i<16;i++){
        float v = ds[t*NC + lane + 32*i];
        P[i] = (__float_as_uint(v) << 9) | (u32)(i*32 + lane);
    }
    BITONIC16U(P);

    u32 sel = 0;
    #pragma unroll
    for(int j=0;j<16;j++){
        u32 m = __reduce_min_sync(0xffffffffu, P[0]);
        if(lane == j) sel = m;
        bool take = (P[0] == m);      // packed values unique -> exactly one lane
        #pragma unroll
        for(int i=0;i<15;i++) P[i] = take ? P[i+1] : P[i];
        P[15] = take ? 0xFFFFFFFFu : P[15];
    }

    if(lane < 16){
        u32 c = sel & 511u;
        float d = __uint_as_float(0x45000000u | (sel >> 9));  // exact key
        float m0 = __shfl_sync(0x0000ffffu, d, 0);
        float e = expf(m0 - d);
        float s = e;
        #pragma unroll
        for(int o=8;o>=1;o>>=1) s += __shfl_xor_sync(0x0000ffffu, s, o);
        g_scores[gt*16 + lane] = e / s;
        g_idx[gt*16 + lane]    = (int)c;
        atomicAdd(&g_cnt[c], 1);
    }
}

// ---------------- K1: fused distance GEMM + branchless top-16 + softmax --------
// (R11 configuration: 55.8us measured)
// block: 32 tokens x 512 centers.  512 thr = 16 warps; warp w owns 32 centers.
// smem 72KB -> L1 carveout ~156KB keeps g_ctrT (128KB) L1-resident.
__global__ __launch_bounds__(512,1) void k_fused(const float* __restrict__ x){
    extern __shared__ char smraw[];
    float* xs  = (float*)smraw;            // 32*64    swizzled x tile (8KB)
    float* ds  = xs + 32*64;               // 32*512   distance keys   (64KB)

    int tid = threadIdx.x;
    int ttile = blockIdx.x*32;

    // load x tile (32 tokens), swizzled xs[r*64 + (k ^ 8*(r&3))]
    const float4* x4 = (const float4*)x;
    {
        int rr = tid >> 4, seg = tid & 15;
        float4 v = x4[(ttile+rr)*16 + seg];
        *(float4*)&xs[rr*64 + ((seg*4) ^ ((rr&3)*8))] = v;
    }
    __syncthreads();

    int w  = tid >> 5, lane = tid & 31;
    int og = lane & 7, tg = lane >> 3;     // tg in 0..3
    int cb = w*32 + og*4;                  // this thread's 4 centers
    int xsw = tg*8;

    u64 acc[8][2];
    #pragma unroll
    for(int i=0;i<8;i++){ acc[i][0]=0; acc[i][1]=0; }

    #pragma unroll 2
    for(int k4=0;k4<16;k4++){
        float v4[8][4];
        #pragma unroll
        for(int i=0;i<8;i++)
            *(float4*)v4[i] = *(const float4*)&xs[(tg+4*i)*64 + ((k4*4) ^ xsw)];
        #pragma unroll
        for(int kk=0;kk<4;kk++){
            int k = k4*4 + kk;
            ulonglong2 p0 = *(const ulonglong2*)&g_ctrT[k*NC + cb];
            #pragma unroll
            for(int i=0;i<8;i++){
                u64 xv = dupf(v4[i][kk]);
                ffma2(acc[i][0], xv, p0.x);
                ffma2(acc[i][1], xv, p0.y);
            }
        }
    }
    // key = c2b - 2*(x.c), write to ds
    {
        ulonglong2 q0 = *(const ulonglong2*)&g_c2[cb];
        u64 m2 = dupf(-2.0f);
        #pragma unroll
        for(int i=0;i<8;i++){
            int r = tg + 4*i;
            *(ulonglong2*)&ds[r*NC + cb] =
                make_ulonglong2(ffma2v(acc[i][0], m2, q0.x),
                                ffma2v(acc[i][1], m2, q0.y));
        }
    }
    __syncthreads();

    // selection: warp w handles tokens 2w, 2w+1
    select16(ds, w*2,     lane, ttile + w*2);
    select16(ds, w*2 + 1, lane, ttile + w*2 + 1);
}

// ---------------- K2: fused scan (block 0) + scatter (all 512 blocks) ----------
__global__ __launch_bounds__(512) void k_ss(){
    __shared__ int wsum[16];
    int tid = threadIdx.x;

    if(blockIdx.x == 0){
        int c = tid, lane = c & 31, w = c >> 5;
        int cn = g_cnt[c];
        int s = cn;
        #pragma unroll
        for(int o=1;o<32;o<<=1){ int v=__shfl_up_sync(0xffffffffu,s,o); if(lane>=o) s+=v; }
        if(lane==31) wsum[w] = s;
        __syncthreads();
        if(w==0){
            int t = (lane<16) ? wsum[lane] : 0;
            #pragma unroll
            for(int o=1;o<16;o<<=1){ int v=__shfl_up_sync(0xffffffffu,t,o); if(lane>=o) t+=v; }
            if(lane<16) wsum[lane] = t;
        }
        __syncthreads();
        int inc = s + ((w>0) ? wsum[w-1] : 0);
        g_off[c] = inc - cn;
        g_cursor[c] = inc - cn;

        int t = (cn + 127) >> 7;
        __syncthreads();
        int s2 = t;
        #pragma unroll
        for(int o=1;o<32;o<<=1){ int v=__shfl_up_sync(0xffffffffu,s2,o); if(lane>=o) s2+=v; }
        if(lane==31) wsum[w] = s2;
        __syncthreads();
        if(w==0){
            int tt = (lane<16) ? wsum[lane] : 0;
            #pragma unroll
            for(int o=1;o<16;o<<=1){ int v=__shfl_up_sync(0xffffffffu,tt,o); if(lane>=o) tt+=v; }
            if(lane<16) wsum[lane] = tt;
        }
        __syncthreads();
        int tinc = s2 + ((w>0) ? wsum[w-1] : 0);
        int tb = tinc - t;
        for(int i=0;i<t;i++){
            g_tiles[2*(tb+i)]   = c;
            g_tiles[2*(tb+i)+1] = i << 7;
        }
        if(c == 511) g_ntiles = tinc;
        __threadfence();
        __syncthreads();
        if(tid == 0) *((volatile int*)&g_flag) = 1;
    } else {
        if(tid == 0){ while(*((volatile int*)&g_flag) == 0){ } }
        __syncthreads();
    }

    int a = blockIdx.x*512 + tid;          // (token<<4)|j
    int c = g_idx[a];
    float s = g_scores[a];
    int pos = atomicAdd(&g_cursor[c], 1);
    g_tok[pos]   = a >> 4;
    g_ascore[pos]= s;
    g_dslot[pos] = a;
}

// ---------------- K3: grouped GEMM, token-pair packed --------------------------
// 128 thr, occ 3.  FFMA2 packs TWO TOKENS: a = (x_t0, x_t1), b = (w, w) from
// pre-duplicated smem wsd (80B group stride: conflict-free LDS.128).
// x tile stored pair-interleaved xp[p][2k+q] (520B rows: conflict-free).
// thread tile = 8 rows (4 pairs) x 8 cols; per k: 8 LDS + 32 FFMA2, no MOVs.
// Warp w owns rows [32w, 32w+32): whole-warp skip when 32w >= m.
__global__ __launch_bounds__(128,3) void k_gemm(const float* __restrict__ x,
                                                const float* __restrict__ Wv,
                                                const float* __restrict__ Ov){
    __shared__ u64   wsd[64*80];     // 40KB: wsd[k*80 + g*10 + j] = (w,w), c=g*8+j
    __shared__ float xp[64*NXP];     // 33.3KB: xp[p*NXP + 2k + q], token = 2p+q
    __shared__ int s_tile;
    int nt = g_ntiles;
    int tid = threadIdx.x;
    int og = tid & 7, tg = tid >> 3;     // tg 0..15, rows tg*8..tg*8+7
    int w  = tid >> 5;
    const float4* x4 = (const float4*)x;

    while(true){
        __syncthreads();             // smem reuse + s_tile protection
        if(tid == 0) s_tile = atomicAdd(&g_work, 1);
        __syncthreads();
        int tile = s_tile;
        if(tile >= nt) break;

        int c      = g_tiles[2*tile];
        int rstart = g_tiles[2*tile+1];
        int base   = g_off[c] + rstart;
        int m      = g_cnt[c] - rstart; if(m > 128) m = 128;

        // fill duplicated weights
        const float4* wv4 = (const float4*)(Wv + (size_t)c*4096);
        #pragma unroll
        for(int f=0; f<8; f++){
            int idx = tid + 128*f;           // 1024 float4s
            int k = idx >> 4, seg = idx & 15;
            float4 v = wv4[idx];
            u64* dst = &wsd[k*80 + (seg>>1)*10 + (seg&1)*4];
            dst[0] = dupf(v.x); dst[1] = dupf(v.y);
            dst[2] = dupf(v.z); dst[3] = dupf(v.w);
        }
        // fill pair-interleaved x: thread owns token row tid
        if(tid < m){
            int tok = g_tok[base + tid];
            float* dst = &xp[(tid>>1)*NXP + (tid&1)];
            #pragma unroll
            for(int seg=0; seg<16; seg++){
                float4 v = x4[tok*16 + seg];
                dst[8*seg + 0] = v.x;
                dst[8*seg + 2] = v.y;
                dst[8*seg + 4] = v.z;
                dst[8*seg + 6] = v.w;
            }
        }
        __syncthreads();

        if(32*w < m){                   // warp-uniform: skip padded rows
            u64 acc[4][8];
            #pragma unroll
            for(int pi=0;pi<4;pi++)
                #pragma unroll
                for(int ci=0;ci<8;ci++) acc[pi][ci] = 0;

            #pragma unroll 4
            for(int k=0;k<64;k++){
                u64 xv[4];
                #pragma unroll
                for(int pi=0;pi<4;pi++)
                    xv[pi] = *(const u64*)&xp[(tg*4+pi)*NXP + 2*k];
                u64 wd[8];
                *(ulonglong2*)&wd[0] = *(const ulonglong2*)&wsd[k*80 + og*10 + 0];
                *(ulonglong2*)&wd[2] = *(const ulonglong2*)&wsd[k*80 + og*10 + 2];
                *(ulonglong2*)&wd[4] = *(const ulonglong2*)&wsd[k*80 + og*10 + 4];
                *(ulonglong2*)&wd[6] = *(const ulonglong2*)&wsd[k*80 + og*10 + 6];
                #pragma unroll
                for(int pi=0;pi<4;pi++)
                    #pragma unroll
                    for(int ci=0;ci<8;ci++)
                        ffma2(acc[pi][ci], xv[pi], wd[ci]);
            }

            float4 ovA = *(const float4*)&Ov[(size_t)c*64 + og*8];
            float4 ovB = *(const float4*)&Ov[(size_t)c*64 + og*8 + 4];
            u64 ovd[8];
            ovd[0]=dupf(ovA.x); ovd[1]=dupf(ovA.y); ovd[2]=dupf(ovA.z); ovd[3]=dupf(ovA.w);
            ovd[4]=dupf(ovB.x); ovd[5]=dupf(ovB.y); ovd[6]=dupf(ovB.z); ovd[7]=dupf(ovB.w);

            #pragma unroll
            for(int pi=0;pi<4;pi++){
                int r0 = (tg*4+pi)*2, r1 = r0 + 1;
                if(r0 < m){
                    float s0 = g_ascore[base + r0];
                    float s1 = (r1 < m) ? g_ascore[base + r1] : 0.0f;
                    u64 sv = pk(s0, s1);
                    u64 t[8];
                    #pragma unroll
                    for(int ci=0;ci<8;ci++)
                        t[ci] = fmul2(fadd2(acc[pi][ci], ovd[ci]), sv);
                    int slot0 = g_dslot[base + r0];
                    float* d0 = &g_part[(size_t)slot0*64 + og*8];
                    *(float4*)&d0[0] = make_float4(lo2(t[0]),lo2(t[1]),lo2(t[2]),lo2(t[3]));
                    *(float4*)&d0[4] = make_float4(lo2(t[4]),lo2(t[5]),lo2(t[6]),lo2(t[7]));
                    if(r1 < m){
                        int slot1 = g_dslot[base + r1];
                        float* d1 = &g_part[(size_t)slot1*64 + og*8];
                        *(float4*)&d1[0] = make_float4(hi2(t[0]),hi2(t[1]),hi2(t[2]),hi2(t[3]));
                        *(float4*)&d1[4] = make_float4(hi2(t[4]),hi2(t[5]),hi2(t[6]),hi2(t[7]));
                    }
                }
            }
        }
    }
}

// ---------------- K4: streamed reduce of 16 contiguous partials per token ------
__global__ __launch_bounds__(256) void k_reduce(float* __restrict__ out){
    int t  = blockIdx.x*16 + (threadIdx.x >> 4);
    int c4 = threadIdx.x & 15;
    const float4* p = (const float4*)(g_part + (size_t)t*16*64) + c4;
    float4 acc = make_float4(0.f,0.f,0.f,0.f);
    #pragma unroll
    for(int j=0;j<16;j++){
        float4 v = p[j*16];
        acc.x += v.x; acc.y += v.y; acc.z += v.z; acc.w += v.w;
    }
    ((float4*)out)[t*16 + c4] = acc;
}

// ---------------- launch -------------------------------------------------------
extern "C" void kernel_launch(void* const* d_in, const int* in_sizes, int n_in,
                              void* d_out, int out_size){
    const float* x    = (const float*)d_in[0];
    const float* ctrs = (const float*)d_in[1];
    const float* Wv   = (const float*)d_in[2];
    const float* Ov   = (const float*)d_in[3];
    float* out = (float*)d_out;

    const int FUSED_SMEM = (32*64 + 32*NC)*4;   // 72 KB
    cudaFuncSetAttribute(k_fused, cudaFuncAttributeMaxDynamicSharedMemorySize,
                         FUSED_SMEM);

    k_prep_t<<<128, 256>>>(ctrs);
    k_prep_c<<<2, 256>>>(ctrs);
    k_prep_z<<<2, 256>>>();
    k_fused <<<512, 512, FUSED_SMEM>>>(x);   // launch #4 -> ncu capture target
    k_ss    <<<512, 512>>>();
    k_gemm  <<<444, 128>>>(x, Wv, Ov);
    k_reduce<<<1024, 256>>>(out);
}

// round 14
// speedup vs baseline: 1.1426x; 1.1167x over previous
#include <cuda_runtime.h>
#include <cstdint>

#define NTOK 16384
#define DIN 64
#define DOUT 64
#define NC 512
#define KSEL 16
#define NASSIGN (NTOK*KSEL)

typedef unsigned long long u64;
typedef unsigned int u32;

// ---------------- scratch (device globals: no allocation allowed) -------------
__device__ float g_ctrT[DIN*NC];        // centers transposed [k][c]
__device__ float g_scores[NASSIGN];     // softmax scores per (token, j)
__device__ int   g_idx[NASSIGN];        // selected center per (token, j)
__device__ int   g_cnt[NC];
__device__ int   g_off[NC];
__device__ int   g_cursor[NC];
__device__ int   g_tok[NASSIGN];        // bucket -> token id
__device__ float g_ascore[NASSIGN];     // bucket -> score
__device__ int   g_dslot[NASSIGN];      // bucket -> (token*16+j) destination slot
__device__ float g_part[(size_t)NASSIGN*DOUT]; // 67 MB partials, slot-addressed
__device__ float g_c2[NC];              // ||c||^2 + 3072 bias
__device__ int   g_tiles[8192];         // (center, rowStart) pairs
__device__ int   g_ntiles;
__device__ int   g_work;                // dynamic tile cursor for k_gemm
__device__ int   g_flag;                // scan-done flag for k_ss

// ---------------- packed f32x2 helpers ----------------------------------------
__device__ __forceinline__ u64 dupf(float x){
    u64 r; asm("mov.b64 %0, {%1, %1};" : "=l"(r) : "f"(x)); return r;
}
__device__ __forceinline__ void ffma2(u64 &d, u64 a, u64 b){
    asm("fma.rn.f32x2 %0, %1, %2, %0;" : "+l"(d) : "l"(a), "l"(b));
}
__device__ __forceinline__ u64 ffma2v(u64 a, u64 b, u64 c){
    u64 d; asm("fma.rn.f32x2 %0, %1, %2, %3;" : "=l"(d) : "l"(a), "l"(b), "l"(c)); return d;
}
__device__ __forceinline__ u64 fadd2(u64 a, u64 b){
    u64 r; asm("add.rn.f32x2 %0, %1, %2;" : "=l"(r) : "l"(a), "l"(b)); return r;
}
__device__ __forceinline__ u64 fmul2(u64 a, u64 b){
    u64 r; asm("mul.rn.f32x2 %0, %1, %2;" : "=l"(r) : "l"(a), "l"(b)); return r;
}

// bitonic sort of 16 u32 ascending: every CAS = 2 IMNMX.
#define BITONIC16U(P) do{ \
    _Pragma("unroll") \
    for(int k_=2;k_<=16;k_<<=1){ \
        _Pragma("unroll") \
        for(int j_=k_>>1;j_>0;j_>>=1){ \
            _Pragma("unroll") \
            for(int i_=0;i_<16;i_++){ \
                int l_=i_^j_; \
                if(l_>i_){ \
                    u32 a_=P[i_], b_=P[l_]; \
                    u32 lo_ = a_<b_?a_:b_, hi_ = a_<b_?b_:a_; \
                    if((i_&k_)==0){ P[i_]=lo_; P[l_]=hi_; } \
                    else          { P[i_]=hi_; P[l_]=lo_; } \
                } \
            } \
        } \
    } }while(0)

// ---------------- K0a: transpose centers ---------------------------------------
__global__ void k_prep_t(const float* __restrict__ ctrs){
    int e = blockIdx.x*256 + threadIdx.x;   // 32768 elements
    int k = e >> 9, c = e & 511;
    g_ctrT[k*NC + c] = ctrs[c*DIN + k];
}

// ---------------- K0b: c2 (+bias 3072, single-binade trick) + zero counters ----
__global__ void k_prep_cz(const float* __restrict__ ctrs){
    int c = blockIdx.x*256 + threadIdx.x;   // 512 centers
    g_cnt[c] = 0;
    if(c == 0){ g_work = 0; g_flag = 0; }
    const float4* c4 = (const float4*)ctrs;
    float s = 3072.0f;   // keys stay in [2048,4096): mantissa order is exact
    #pragma unroll
    for(int seg=0; seg<16; seg++){
        float4 v = c4[c*16 + seg];
        s += v.x*v.x + v.y*v.y + v.z*v.z + v.w*v.w;
    }
    g_c2[c] = s;
}

// ---------------- per-token branchless top-16 + softmax (u32 packed) -----------
__device__ __forceinline__ void select16(const float* ds, int t, int lane,
                                         int gt){
    u32 P[16];
    #pragma unroll
    for(int i=0;i<16;i++){
        float v = ds[t*NC + lane + 32*i];
        P[i] = (__float_as_uint(v) << 9) | (u32)(i*32 + lane);
    }
    BITONIC16U(P);

    u32 sel = 0;
    #pragma unroll
    for(int j=0;j<16;j++){
        u32 m = __reduce_min_sync(0xffffffffu, P[0]);
        if(lane == j) sel = m;
        bool take = (P[0] == m);      // packed values unique -> exactly one lane
        #pragma unroll
        for(int i=0;i<15;i++) P[i] = take ? P[i+1] : P[i];
        P[15] = take ? 0xFFFFFFFFu : P[15];
    }

    if(lane < 16){
        u32 c = sel & 511u;
        float d = __uint_as_float(0x45000000u | (sel >> 9));  // exact key
        float m0 = __shfl_sync(0x0000ffffu, d, 0);
        float e = expf(m0 - d);
        float s = e;
        #pragma unroll
        for(int o=8;o>=1;o>>=1) s += __shfl_xor_sync(0x0000ffffu, s, o);
        g_scores[gt*16 + lane] = e / s;
        g_idx[gt*16 + lane]    = (int)c;
        atomicAdd(&g_cnt[c], 1);
    }
}

// ---------------- K1: fused distance GEMM + branchless top-16 + softmax --------
// PERSISTENT: 148 blocks x 512 thr; 1024 tiles of 16 tokens x 512 centers
// (7 tiles max/block -> 98.8% utilization vs 86.5% at 32-token tiles).
// warp w owns 32 centers; thread = 4 tokens x 4 centers (acc 16 regs).
// smem 36KB -> g_ctrT (128KB) stays L1-resident.
__global__ __launch_bounds__(512,1) void k_fused(const float* __restrict__ x){
    extern __shared__ char smraw[];
    float* xs  = (float*)smraw;            // 16*64    swizzled x tile (4KB)
    float* ds  = xs + 16*64;               // 16*512   distance keys  (32KB)

    int tid = threadIdx.x;
    int w  = tid >> 5, lane = tid & 31;
    int og = lane & 7, tg = lane >> 3;     // tg in 0..3
    int cb = w*32 + og*4;                  // this thread's 4 centers
    int xsw = tg*8;
    const float4* x4 = (const float4*)x;

    for(int tile = blockIdx.x; tile < 1024; tile += 148){
        int ttile = tile*16;
        __syncthreads();                   // prev selection reads done
        if(tid < 256){                     // 16 tokens x 16 float4
            int rr = tid >> 4, seg = tid & 15;
            float4 v = x4[(ttile+rr)*16 + seg];
            *(float4*)&xs[rr*64 + ((seg*4) ^ ((rr&3)*8))] = v;
        }
        __syncthreads();

        u64 acc[4][2];
        #pragma unroll
        for(int i=0;i<4;i++){ acc[i][0]=0; acc[i][1]=0; }

        #pragma unroll 2
        for(int k4=0;k4<16;k4++){
            float v4[4][4];
            #pragma unroll
            for(int i=0;i<4;i++)
                *(float4*)v4[i] = *(const float4*)&xs[(tg+4*i)*64 + ((k4*4) ^ xsw)];
            #pragma unroll
            for(int kk=0;kk<4;kk++){
                int k = k4*4 + kk;
                ulonglong2 p0 = *(const ulonglong2*)&g_ctrT[k*NC + cb];
                #pragma unroll
                for(int i=0;i<4;i++){
                    u64 xv = dupf(v4[i][kk]);
                    ffma2(acc[i][0], xv, p0.x);
                    ffma2(acc[i][1], xv, p0.y);
                }
            }
        }
        // key = c2b - 2*(x.c), write to ds
        {
            ulonglong2 q0 = *(const ulonglong2*)&g_c2[cb];
            u64 m2 = dupf(-2.0f);
            #pragma unroll
            for(int i=0;i<4;i++){
                int r = tg + 4*i;
                *(ulonglong2*)&ds[r*NC + cb] =
                    make_ulonglong2(ffma2v(acc[i][0], m2, q0.x),
                                    ffma2v(acc[i][1], m2, q0.y));
            }
        }
        __syncthreads();

        // selection: warp w handles token w (16 warps, 16 tokens)
        select16(ds, w, lane, ttile + w);
    }
}

// ---------------- K2: fused scan (block 0) + scatter (all 512 blocks) ----------
__global__ __launch_bounds__(512) void k_ss(){
    __shared__ int wsum[16];
    int tid = threadIdx.x;

    if(blockIdx.x == 0){
        int c = tid, lane = c & 31, w = c >> 5;
        int cn = g_cnt[c];
        int s = cn;
        #pragma unroll
        for(int o=1;o<32;o<<=1){ int v=__shfl_up_sync(0xffffffffu,s,o); if(lane>=o) s+=v; }
        if(lane==31) wsum[w] = s;
        __syncthreads();
        if(w==0){
            int t = (lane<16) ? wsum[lane] : 0;
            #pragma unroll
            for(int o=1;o<16;o<<=1){ int v=__shfl_up_sync(0xffffffffu,t,o); if(lane>=o) t+=v; }
            if(lane<16) wsum[lane] = t;
        }
        __syncthreads();
        int inc = s + ((w>0) ? wsum[w-1] : 0);
        g_off[c] = inc - cn;
        g_cursor[c] = inc - cn;

        int t = (cn + 127) >> 7;
        __syncthreads();
        int s2 = t;
        #pragma unroll
        for(int o=1;o<32;o<<=1){ int v=__shfl_up_sync(0xffffffffu,s2,o); if(lane>=o) s2+=v; }
        if(lane==31) wsum[w] = s2;
        __syncthreads();
        if(w==0){
            int tt = (lane<16) ? wsum[lane] : 0;
            #pragma unroll
            for(int o=1;o<16;o<<=1){ int v=__shfl_up_sync(0xffffffffu,tt,o); if(lane>=o) tt+=v; }
            if(lane<16) wsum[lane] = tt;
        }
        __syncthreads();
        int tinc = s2 + ((w>0) ? wsum[w-1] : 0);
        int tb = tinc - t;
        for(int i=0;i<t;i++){
            g_tiles[2*(tb+i)]   = c;
            g_tiles[2*(tb+i)+1] = i << 7;
        }
        if(c == 511) g_ntiles = tinc;
        __threadfence();
        __syncthreads();
        if(tid == 0) *((volatile int*)&g_flag) = 1;
    } else {
        if(tid == 0){ while(*((volatile int*)&g_flag) == 0){ } }
        __syncthreads();
    }

    int a = blockIdx.x*512 + tid;          // (token<<4)|j
    int c = g_idx[a];
    float s = g_scores[a];
    int pos = atomicAdd(&g_cursor[c], 1);
    g_tok[pos]   = a >> 4;
    g_ascore[pos]= s;
    g_dslot[pos] = a;
}

// ---------------- K3: grouped GEMM per (center, 128-row tile) ------------------
// (R5/R11 config, 60.5us measured)
// 256 thr, thread tile 4 rows x 8 cols (split og*4 / og*4+32).
// Warp w owns rows [16w, 16w+16): whole-warp skip when 16w >= m.
__global__ __launch_bounds__(256,3) void k_gemm(const float* __restrict__ x,
                                                const float* __restrict__ Wv,
                                                const float* __restrict__ Ov){
    __shared__ float ws[DIN*DOUT];   // ws[k*64 + p] (row-major copy of Wv[c])
    __shared__ float xs[128*DIN];    // xs[r*64 + (k ^ 8*((r>>2)&3))]
    __shared__ int s_tile;
    int nt = g_ntiles;
    int tid = threadIdx.x;
    int og = tid & 7, tg = tid >> 3;     // tg 0..31
    int w  = tid >> 5;
    int xsw = (tg & 3) * 8;              // rows tg*4..tg*4+3 share (r>>2)&3 == tg&3
    const float4* x4 = (const float4*)x;

    while(true){
        __syncthreads();             // smem reuse + s_tile protection
        if(tid == 0) s_tile = atomicAdd(&g_work, 1);
        __syncthreads();
        int tile = s_tile;
        if(tile >= nt) break;

        int c      = g_tiles[2*tile];
        int rstart = g_tiles[2*tile+1];
        int base   = g_off[c] + rstart;
        int m      = g_cnt[c] - rstart; if(m > 128) m = 128;

        const float4* wv4 = (const float4*)(Wv + (size_t)c*4096);
        float4* ws4 = (float4*)ws;
        #pragma unroll
        for(int f=0; f<4; f++) ws4[tid + 256*f] = wv4[tid + 256*f];

        #pragma unroll
        for(int it=0; it<8; it++){
            int idx2 = tid + 256*it;
            int rr = idx2 >> 4, seg = idx2 & 15;
            if(rr < m){
                float4 v = x4[g_tok[base+rr]*16 + seg];
                *(float4*)&xs[rr*64 + ((seg*4) ^ (((rr>>2)&3)*8))] = v;
            }
        }
        __syncthreads();

        if(16*w < m){                   // warp-uniform: skip padded rows
            u64 acc[4][4];
            #pragma unroll
            for(int i=0;i<4;i++){ acc[i][0]=0; acc[i][1]=0; acc[i][2]=0; acc[i][3]=0; }

            #pragma unroll 4
            for(int k4=0;k4<16;k4++){
                float v4[4][4];
                #pragma unroll
                for(int i=0;i<4;i++)
                    *(float4*)v4[i] = *(const float4*)&xs[(tg*4+i)*64 + ((k4*4) ^ xsw)];
                #pragma unroll
                for(int kk=0;kk<4;kk++){
                    int k = k4*4 + kk;
                    ulonglong2 p0 = *(const ulonglong2*)&ws[k*64 + og*4];
                    ulonglong2 p1 = *(const ulonglong2*)&ws[k*64 + og*4 + 32];
                    #pragma unroll
                    for(int i=0;i<4;i++){
                        u64 xv = dupf(v4[i][kk]);
                        ffma2(acc[i][0], xv, p0.x);
                        ffma2(acc[i][1], xv, p0.y);
                        ffma2(acc[i][2], xv, p1.x);
                        ffma2(acc[i][3], xv, p1.y);
                    }
                }
            }
            ulonglong2 q0 = *(const ulonglong2*)&Ov[(size_t)c*64 + og*4];
            ulonglong2 q1 = *(const ulonglong2*)&Ov[(size_t)c*64 + og*4 + 32];
            #pragma unroll
            for(int i=0;i<4;i++){
                int r = tg*4 + i;
                if(r < m){
                    int slot = g_dslot[base + r];
                    u64 sv = dupf(g_ascore[base + r]);
                    ulonglong2* d0 = (ulonglong2*)&g_part[(size_t)slot*64 + og*4];
                    ulonglong2* d1 = (ulonglong2*)&g_part[(size_t)slot*64 + og*4 + 32];
                    *d0 = make_ulonglong2(fmul2(fadd2(acc[i][0], q0.x), sv),
                                          fmul2(fadd2(acc[i][1], q0.y), sv));
                    *d1 = make_ulonglong2(fmul2(fadd2(acc[i][2], q1.x), sv),
                                          fmul2(fadd2(acc[i][3], q1.y), sv));
                }
            }
        }
    }
}

// ---------------- K4: streamed reduce of 16 contiguous partials per token ------
__global__ __launch_bounds__(256) void k_reduce(float* __restrict__ out){
    int t  = blockIdx.x*16 + (threadIdx.x >> 4);
    int c4 = threadIdx.x & 15;
    const float4* p = (const float4*)(g_part + (size_t)t*16*64) + c4;
    float4 acc = make_float4(0.f,0.f,0.f,0.f);
    #pragma unroll
    for(int j=0;j<16;j++){
        float4 v = p[j*16];
        acc.x += v.x; acc.y += v.y; acc.z += v.z; acc.w += v.w;
    }
    ((float4*)out)[t*16 + c4] = acc;
}

// ---------------- launch -------------------------------------------------------
extern "C" void kernel_launch(void* const* d_in, const int* in_sizes, int n_in,
                              void* d_out, int out_size){
    const float* x    = (const float*)d_in[0];
    const float* ctrs = (const float*)d_in[1];
    const float* Wv   = (const float*)d_in[2];
    const float* Ov   = (const float*)d_in[3];
    float* out = (float*)d_out;

    const int FUSED_SMEM = (16*64 + 16*NC)*4;   // 36 KB
    cudaFuncSetAttribute(k_fused, cudaFuncAttributeMaxDynamicSharedMemorySize,
                         FUSED_SMEM);

    k_prep_t <<<128, 256>>>(ctrs);
    k_prep_cz<<<2, 256>>>(ctrs);
    k_fused  <<<148, 512, FUSED_SMEM>>>(x);
    k_ss     <<<512, 512>>>();          // launch #4 -> ncu capture target
    k_gemm   <<<444, 256>>>(x, Wv, Ov);
    k_reduce <<<1024, 256>>>(out);
}

// round 15
// speedup vs baseline: 1.4048x; 1.2294x over previous
#include <cuda_runtime.h>
#include <cstdint>

#define NTOK 16384
#define DIN 64
#define DOUT 64
#define NC 512
#define KSEL 16
#define NASSIGN (NTOK*KSEL)
#define CAP 16384        // fixed per-center bucket capacity (max possible)

typedef unsigned long long u64;
typedef unsigned int u32;

// ---------------- scratch (device globals: no allocation allowed) -------------
__device__ float g_ctrT[DIN*NC];        // centers transposed [k][c]
__device__ float g_scores[NASSIGN];     // softmax scores per (token, j)
__device__ int   g_idx[NASSIGN];        // selected center per (token, j)
__device__ int   g_rank[NASSIGN];       // per-center rank (from k_fused atomic)
__device__ int   g_cnt[NC];
__device__ int   g_tok[(size_t)NC*CAP];    // bucket slot -> token id
__device__ float g_ascore[(size_t)NC*CAP]; // bucket slot -> score
__device__ int   g_dslot[(size_t)NC*CAP];  // bucket slot -> (token*16+j)
__device__ float g_part[(size_t)NASSIGN*DOUT]; // 67 MB partials, slot-addressed
__device__ float g_c2[NC];              // ||c||^2 + 3072 bias
__device__ int   g_tiles[8192];         // (center, rowStart) pairs
__device__ int   g_ntiles;
__device__ int   g_work;                // dynamic tile cursor for k_gemm

// ---------------- packed f32x2 helpers ----------------------------------------
__device__ __forceinline__ u64 dupf(float x){
    u64 r; asm("mov.b64 %0, {%1, %1};" : "=l"(r) : "f"(x)); return r;
}
__device__ __forceinline__ void ffma2(u64 &d, u64 a, u64 b){
    asm("fma.rn.f32x2 %0, %1, %2, %0;" : "+l"(d) : "l"(a), "l"(b));
}
__device__ __forceinline__ u64 ffma2v(u64 a, u64 b, u64 c){
    u64 d; asm("fma.rn.f32x2 %0, %1, %2, %3;" : "=l"(d) : "l"(a), "l"(b), "l"(c)); return d;
}
__device__ __forceinline__ u64 fadd2(u64 a, u64 b){
    u64 r; asm("add.rn.f32x2 %0, %1, %2;" : "=l"(r) : "l"(a), "l"(b)); return r;
}
__device__ __forceinline__ u64 fmul2(u64 a, u64 b){
    u64 r; asm("mul.rn.f32x2 %0, %1, %2;" : "=l"(r) : "l"(a), "l"(b)); return r;
}

// bitonic sort of 16 u32 ascending: every CAS = 2 IMNMX.
#define BITONIC16U(P) do{ \
    _Pragma("unroll") \
    for(int k_=2;k_<=16;k_<<=1){ \
        _Pragma("unroll") \
        for(int j_=k_>>1;j_>0;j_>>=1){ \
            _Pragma("unroll") \
            for(int i_=0;i_<16;i_++){ \
                int l_=i_^j_; \
                if(l_>i_){ \
                    u32 a_=P[i_], b_=P[l_]; \
                    u32 lo_ = a_<b_?a_:b_, hi_ = a_<b_?b_:a_; \
                    if((i_&k_)==0){ P[i_]=lo_; P[l_]=hi_; } \
                    else          { P[i_]=hi_; P[l_]=lo_; } \
                } \
            } \
        } \
    } }while(0)

// ---------------- K0a: transpose centers ---------------------------------------
__global__ void k_prep_t(const float* __restrict__ ctrs){
    int e = blockIdx.x*256 + threadIdx.x;   // 32768 elements
    int k = e >> 9, c = e & 511;
    g_ctrT[k*NC + c] = ctrs[c*DIN + k];
}

// ---------------- K0b: c2 (+bias 3072, single-binade trick) + zero counters ----
__global__ void k_prep_cz(const float* __restrict__ ctrs){
    int c = blockIdx.x*256 + threadIdx.x;   // 512 centers
    g_cnt[c] = 0;
    if(c == 0) g_work = 0;
    const float4* c4 = (const float4*)ctrs;
    float s = 3072.0f;   // keys stay in [2048,4096): mantissa order is exact
    #pragma unroll
    for(int seg=0; seg<16; seg++){
        float4 v = c4[c*16 + seg];
        s += v.x*v.x + v.y*v.y + v.z*v.z + v.w*v.w;
    }
    g_c2[c] = s;
}

// ---------------- per-token branchless top-16 + softmax (u32 packed) -----------
__device__ __forceinline__ void select16(const float* ds, int t, int lane,
                                         int gt){
    u32 P[16];
    #pragma unroll
    for(int i=0;i<16;i++){
        float v = ds[t*NC + lane + 32*i];
        P[i] = (__float_as_uint(v) << 9) | (u32)(i*32 + lane);
    }
    BITONIC16U(P);

    u32 sel = 0;
    #pragma unroll
    for(int j=0;j<16;j++){
        u32 m = __reduce_min_sync(0xffffffffu, P[0]);
        if(lane == j) sel = m;
        bool take = (P[0] == m);      // packed values unique -> exactly one lane
        #pragma unroll
        for(int i=0;i<15;i++) P[i] = take ? P[i+1] : P[i];
        P[15] = take ? 0xFFFFFFFFu : P[15];
    }

    if(lane < 16){
        u32 c = sel & 511u;
        float d = __uint_as_float(0x45000000u | (sel >> 9));  // exact key
        float m0 = __shfl_sync(0x0000ffffu, d, 0);
        float e = expf(m0 - d);
        float s = e;
        #pragma unroll
        for(int o=8;o>=1;o>>=1) s += __shfl_xor_sync(0x0000ffffu, s, o);
        g_scores[gt*16 + lane] = e / s;
        g_idx[gt*16 + lane]    = (int)c;
        // rank from the counting atomic: free bucket position, no later scan
        g_rank[gt*16 + lane]   = atomicAdd(&g_cnt[c], 1);
    }
}

// ---------------- K1: fused distance GEMM + branchless top-16 + softmax --------
// PERSISTENT: 148 blocks x 512 thr; 1024 tiles of 16 tokens x 512 centers.
// warp w owns 32 centers; thread = 4 tokens x 4 centers (acc 16 regs).
// smem 36KB -> g_ctrT (128KB) stays L1-resident.
__global__ __launch_bounds__(512,1) void k_fused(const float* __restrict__ x){
    extern __shared__ char smraw[];
    float* xs  = (float*)smraw;            // 16*64    swizzled x tile (4KB)
    float* ds  = xs + 16*64;               // 16*512   distance keys  (32KB)

    int tid = threadIdx.x;
    int w  = tid >> 5, lane = tid & 31;
    int og = lane & 7, tg = lane >> 3;     // tg in 0..3
    int cb = w*32 + og*4;                  // this thread's 4 centers
    int xsw = tg*8;
    const float4* x4 = (const float4*)x;

    for(int tile = blockIdx.x; tile < 1024; tile += 148){
        int ttile = tile*16;
        __syncthreads();                   // prev selection reads done
        if(tid < 256){                     // 16 tokens x 16 float4
            int rr = tid >> 4, seg = tid & 15;
            float4 v = x4[(ttile+rr)*16 + seg];
            *(float4*)&xs[rr*64 + ((seg*4) ^ ((rr&3)*8))] = v;
        }
        __syncthreads();

        u64 acc[4][2];
        #pragma unroll
        for(int i=0;i<4;i++){ acc[i][0]=0; acc[i][1]=0; }

        #pragma unroll 2
        for(int k4=0;k4<16;k4++){
            float v4[4][4];
            #pragma unroll
            for(int i=0;i<4;i++)
                *(float4*)v4[i] = *(const float4*)&xs[(tg+4*i)*64 + ((k4*4) ^ xsw)];
            #pragma unroll
            for(int kk=0;kk<4;kk++){
                int k = k4*4 + kk;
                ulonglong2 p0 = *(const ulonglong2*)&g_ctrT[k*NC + cb];
                #pragma unroll
                for(int i=0;i<4;i++){
                    u64 xv = dupf(v4[i][kk]);
                    ffma2(acc[i][0], xv, p0.x);
                    ffma2(acc[i][1], xv, p0.y);
                }
            }
        }
        // key = c2b - 2*(x.c), write to ds
        {
            ulonglong2 q0 = *(const ulonglong2*)&g_c2[cb];
            u64 m2 = dupf(-2.0f);
            #pragma unroll
            for(int i=0;i<4;i++){
                int r = tg + 4*i;
                *(ulonglong2*)&ds[r*NC + cb] =
                    make_ulonglong2(ffma2v(acc[i][0], m2, q0.x),
                                    ffma2v(acc[i][1], m2, q0.y));
            }
        }
        __syncthreads();

        // selection: warp w handles token w (16 warps, 16 tokens)
        select16(ds, w, lane, ttile + w);
    }
}

// ---------------- K2a: atomic-free scatter into fixed-capacity buckets ---------
__global__ void k_scatter(){
    int a = blockIdx.x*512 + threadIdx.x;   // (token<<4)|j
    int c = g_idx[a];
    size_t pos = (size_t)c*CAP + g_rank[a];
    g_tok[pos]   = a >> 4;
    g_ascore[pos]= g_scores[a];
    g_dslot[pos] = a;
}

// ---------------- K2b: tile-list build (1 block, shuffle scan) ------------------
__global__ __launch_bounds__(512) void k_tiles(){
    __shared__ int wsum[16];
    int c = threadIdx.x, lane = c & 31, w = c >> 5;
    int t = (g_cnt[c] + 127) >> 7;
    int s = t;
    #pragma unroll
    for(int o=1;o<32;o<<=1){ int v=__shfl_up_sync(0xffffffffu,s,o); if(lane>=o) s+=v; }
    if(lane==31) wsum[w] = s;
    __syncthreads();
    if(w==0){
        int tt = (lane<16) ? wsum[lane] : 0;
        #pragma unroll
        for(int o=1;o<16;o<<=1){ int v=__shfl_up_sync(0xffffffffu,tt,o); if(lane>=o) tt+=v; }
        if(lane<16) wsum[lane] = tt;
    }
    __syncthreads();
    int tinc = s + ((w>0) ? wsum[w-1] : 0);
    int tb = tinc - t;
    for(int i=0;i<t;i++){
        g_tiles[2*(tb+i)]   = c;
        g_tiles[2*(tb+i)+1] = i << 7;
    }
    if(c == 511) g_ntiles = tinc;
}

// ---------------- K3: grouped GEMM per (center, 128-row tile) ------------------
// 256 thr, thread tile 4 rows x 8 cols (split og*4 / og*4+32).
// Warp w owns rows [16w, 16w+16): whole-warp skip when 16w >= m.
__global__ __launch_bounds__(256,3) void k_gemm(const float* __restrict__ x,
                                                const float* __restrict__ Wv,
                                                const float* __restrict__ Ov){
    __shared__ float ws[DIN*DOUT];   // ws[k*64 + p] (row-major copy of Wv[c])
    __shared__ float xs[128*DIN];    // xs[r*64 + (k ^ 8*((r>>2)&3))]
    __shared__ int s_tile;
    int nt = g_ntiles;
    int tid = threadIdx.x;
    int og = tid & 7, tg = tid >> 3;     // tg 0..31
    int w  = tid >> 5;
    int xsw = (tg & 3) * 8;              // rows tg*4..tg*4+3 share (r>>2)&3 == tg&3
    const float4* x4 = (const float4*)x;

    while(true){
        __syncthreads();             // smem reuse + s_tile protection
        if(tid == 0) s_tile = atomicAdd(&g_work, 1);
        __syncthreads();
        int tile = s_tile;
        if(tile >= nt) break;

        int c      = g_tiles[2*tile];
        int rstart = g_tiles[2*tile+1];
        size_t base = (size_t)c*CAP + rstart;
        int m      = g_cnt[c] - rstart; if(m > 128) m = 128;

        const float4* wv4 = (const float4*)(Wv + (size_t)c*4096);
        float4* ws4 = (float4*)ws;
        #pragma unroll
        for(int f=0; f<4; f++) ws4[tid + 256*f] = wv4[tid + 256*f];

        #pragma unroll
        for(int it=0; it<8; it++){
            int idx2 = tid + 256*it;
            int rr = idx2 >> 4, seg = idx2 & 15;
            if(rr < m){
                float4 v = x4[g_tok[base+rr]*16 + seg];
                *(float4*)&xs[rr*64 + ((seg*4) ^ (((rr>>2)&3)*8))] = v;
            }
        }
        __syncthreads();

        if(16*w < m){                   // warp-uniform: skip padded rows
            u64 acc[4][4];
            #pragma unroll
            for(int i=0;i<4;i++){ acc[i][0]=0; acc[i][1]=0; acc[i][2]=0; acc[i][3]=0; }

            #pragma unroll 4
            for(int k4=0;k4<16;k4++){
                float v4[4][4];
                #pragma unroll
                for(int i=0;i<4;i++)
                    *(float4*)v4[i] = *(const float4*)&xs[(tg*4+i)*64 + ((k4*4) ^ xsw)];
                #pragma unroll
                for(int kk=0;kk<4;kk++){
                    int k = k4*4 + kk;
                    ulonglong2 p0 = *(const ulonglong2*)&ws[k*64 + og*4];
                    ulonglong2 p1 = *(const ulonglong2*)&ws[k*64 + og*4 + 32];
                    #pragma unroll
                    for(int i=0;i<4;i++){
                        u64 xv = dupf(v4[i][kk]);
                        ffma2(acc[i][0], xv, p0.x);
                        ffma2(acc[i][1], xv, p0.y);
                        ffma2(acc[i][2], xv, p1.x);
                        ffma2(acc[i][3], xv, p1.y);
                    }
                }
            }
            ulonglong2 q0 = *(const ulonglong2*)&Ov[(size_t)c*64 + og*4];
            ulonglong2 q1 = *(const ulonglong2*)&Ov[(size_t)c*64 + og*4 + 32];
            #pragma unroll
            for(int i=0;i<4;i++){
                int r = tg*4 + i;
                if(r < m){
                    int slot = g_dslot[base + r];
                    u64 sv = dupf(g_ascore[base + r]);
                    ulonglong2* d0 = (ulonglong2*)&g_part[(size_t)slot*64 + og*4];
                    ulonglong2* d1 = (ulonglong2*)&g_part[(size_t)slot*64 + og*4 + 32];
                    *d0 = make_ulonglong2(fmul2(fadd2(acc[i][0], q0.x), sv),
                                          fmul2(fadd2(acc[i][1], q0.y), sv));
                    *d1 = make_ulonglong2(fmul2(fadd2(acc[i][2], q1.x), sv),
                                          fmul2(fadd2(acc[i][3], q1.y), sv));
                }
            }
        }
    }
}

// ---------------- K4: streamed reduce of 16 contiguous partials per token ------
__global__ __launch_bounds__(256) void k_reduce(float* __restrict__ out){
    int t  = blockIdx.x*16 + (threadIdx.x >> 4);
    int c4 = threadIdx.x & 15;
    const float4* p = (const float4*)(g_part + (size_t)t*16*64) + c4;
    float4 acc = make_float4(0.f,0.f,0.f,0.f);
    #pragma unroll
    for(int j=0;j<16;j++){
        float4 v = p[j*16];
        acc.x += v.x; acc.y += v.y; acc.z += v.z; acc.w += v.w;
    }
    ((float4*)out)[t*16 + c4] = acc;
}

// ---------------- launch -------------------------------------------------------
extern "C" void kernel_launch(void* const* d_in, const int* in_sizes, int n_in,
                              void* d_out, int out_size){
    const float* x    = (const float*)d_in[0];
    const float* ctrs = (const float*)d_in[1];
    const float* Wv   = (const float*)d_in[2];
    const float* Ov   = (const float*)d_in[3];
    float* out = (float*)d_out;

    const int FUSED_SMEM = (16*64 + 16*NC)*4;   // 36 KB
    cudaFuncSetAttribute(k_fused, cudaFuncAttributeMaxDynamicSharedMemorySize,
                         FUSED_SMEM);

    k_prep_t <<<128, 256>>>(ctrs);
    k_prep_cz<<<2, 256>>>(ctrs);
    k_fused  <<<148, 512, FUSED_SMEM>>>(x);
    k_scatter<<<512, 512>>>();          // launch #4 -> ncu capture target
    k_tiles  <<<1, 512>>>();
    k_gemm   <<<444, 256>>>(x, Wv, Ov);
    k_reduce <<<1024, 256>>>(out);
}

// round 16
// speedup vs baseline: 1.4532x; 1.0344x over previous
#include <cuda_runtime.h>
#include <cstdint>

#define NTOK 16384
#define DIN 64
#define DOUT 64
#define NC 512
#define KSEL 16
#define NASSIGN (NTOK*KSEL)
#define CAP 16384        // fixed per-center bucket capacity (max possible)

typedef unsigned long long u64;
typedef unsigned int u32;

// ---------------- scratch (device globals: no allocation allowed) -------------
__device__ float g_ctrT[DIN*NC];        // centers transposed [k][c]
__device__ int   g_cnt[NC];
__device__ int   g_tok[(size_t)NC*CAP];    // bucket slot -> token id
__device__ float g_ascore[(size_t)NC*CAP]; // bucket slot -> score
__device__ int   g_dslot[(size_t)NC*CAP];  // bucket slot -> (token*16+j)
__device__ float g_part[(size_t)NASSIGN*DOUT]; // 67 MB partials, slot-addressed
__device__ float g_c2[NC];              // ||c||^2 + 3072 bias
__device__ int   g_tiles[8192];         // (center, rowStart) pairs
__device__ int   g_ntiles;
__device__ int   g_work;                // dynamic tile cursor for k_gemm

// ---------------- packed f32x2 helpers ----------------------------------------
__device__ __forceinline__ u64 dupf(float x){
    u64 r; asm("mov.b64 %0, {%1, %1};" : "=l"(r) : "f"(x)); return r;
}
__device__ __forceinline__ void ffma2(u64 &d, u64 a, u64 b){
    asm("fma.rn.f32x2 %0, %1, %2, %0;" : "+l"(d) : "l"(a), "l"(b));
}
__device__ __forceinline__ u64 ffma2v(u64 a, u64 b, u64 c){
    u64 d; asm("fma.rn.f32x2 %0, %1, %2, %3;" : "=l"(d) : "l"(a), "l"(b), "l"(c)); return d;
}
__device__ __forceinline__ u64 fadd2(u64 a, u64 b){
    u64 r; asm("add.rn.f32x2 %0, %1, %2;" : "=l"(r) : "l"(a), "l"(b)); return r;
}
__device__ __forceinline__ u64 fmul2(u64 a, u64 b){
    u64 r; asm("mul.rn.f32x2 %0, %1, %2;" : "=l"(r) : "l"(a), "l"(b)); return r;
}

// bitonic sort of 16 u32 ascending: every CAS = 2 IMNMX.
#define BITONIC16U(P) do{ \
    _Pragma("unroll") \
    for(int k_=2;k_<=16;k_<<=1){ \
        _Pragma("unroll") \
        for(int j_=k_>>1;j_>0;j_>>=1){ \
            _Pragma("unroll") \
            for(int i_=0;i_<16;i_++){ \
                int l_=i_^j_; \
                if(l_>i_){ \
                    u32 a_=P[i_], b_=P[l_]; \
                    u32 lo_ = a_<b_?a_:b_, hi_ = a_<b_?b_:a_; \
                    if((i_&k_)==0){ P[i_]=lo_; P[l_]=hi_; } \
                    else          { P[i_]=hi_; P[l_]=lo_; } \
                } \
            } \
        } \
    } }while(0)

// ---------------- K0a: transpose centers ---------------------------------------
__global__ void k_prep_t(const float* __restrict__ ctrs){
    int e = blockIdx.x*256 + threadIdx.x;   // 32768 elements
    int k = e >> 9, c = e & 511;
    g_ctrT[k*NC + c] = ctrs[c*DIN + k];
}

// ---------------- K0b: c2 (+bias 3072, single-binade trick) + zero counters ----
__global__ void k_prep_cz(const float* __restrict__ ctrs){
    int c = blockIdx.x*256 + threadIdx.x;   // 512 centers
    g_cnt[c] = 0;
    if(c == 0) g_work = 0;
    const float4* c4 = (const float4*)ctrs;
    float s = 3072.0f;   // keys stay in [2048,4096): mantissa order is exact
    #pragma unroll
    for(int seg=0; seg<16; seg++){
        float4 v = c4[c*16 + seg];
        s += v.x*v.x + v.y*v.y + v.z*v.z + v.w*v.w;
    }
    g_c2[c] = s;
}

// ---------------- per-token branchless top-16 + softmax + DIRECT scatter -------
// The counting atomic returns the bucket rank; the 3 stores go straight into
// the fixed-capacity bucket. Bucket order is timing-dependent but every row's
// VALUE depends only on (token, center) and g_part is dslot-addressed, so the
// final output is bitwise deterministic.
__device__ __forceinline__ void select16(const float* ds, int t, int lane,
                                         int gt){
    u32 P[16];
    #pragma unroll
    for(int i=0;i<16;i++){
        float v = ds[t*NC + lane + 32*i];
        P[i] = (__float_as_uint(v) << 9) | (u32)(i*32 + lane);
    }
    BITONIC16U(P);

    u32 sel = 0;
    #pragma unroll
    for(int j=0;j<16;j++){
        u32 m = __reduce_min_sync(0xffffffffu, P[0]);
        if(lane == j) sel = m;
        bool take = (P[0] == m);      // packed values unique -> exactly one lane
        #pragma unroll
        for(int i=0;i<15;i++) P[i] = take ? P[i+1] : P[i];
        P[15] = take ? 0xFFFFFFFFu : P[15];
    }

    if(lane < 16){
        u32 c = sel & 511u;
        float d = __uint_as_float(0x45000000u | (sel >> 9));  // exact key
        float m0 = __shfl_sync(0x0000ffffu, d, 0);
        float e = expf(m0 - d);
        float s = e;
        #pragma unroll
        for(int o=8;o>=1;o>>=1) s += __shfl_xor_sync(0x0000ffffu, s, o);
        int rank = atomicAdd(&g_cnt[c], 1);
        size_t pos = (size_t)c*CAP + rank;
        g_tok[pos]    = gt;
        g_ascore[pos] = e / s;
        g_dslot[pos]  = gt*16 + lane;
    }
}

// ---------------- K1: fused distance GEMM + top-16 + softmax + scatter ---------
// PERSISTENT: 148 blocks x 512 thr; 1024 tiles of 16 tokens x 512 centers.
// warp w owns 32 centers; thread = 4 tokens x 4 centers (acc 16 regs).
// smem 36KB -> g_ctrT (128KB) stays L1-resident.
__global__ __launch_bounds__(512,1) void k_fused(const float* __restrict__ x){
    extern __shared__ char smraw[];
    float* xs  = (float*)smraw;            // 16*64    swizzled x tile (4KB)
    float* ds  = xs + 16*64;               // 16*512   distance keys  (32KB)

    int tid = threadIdx.x;
    int w  = tid >> 5, lane = tid & 31;
    int og = lane & 7, tg = lane >> 3;     // tg in 0..3
    int cb = w*32 + og*4;                  // this thread's 4 centers
    int xsw = tg*8;
    const float4* x4 = (const float4*)x;

    for(int tile = blockIdx.x; tile < 1024; tile += 148){
        int ttile = tile*16;
        __syncthreads();                   // prev selection reads done
        if(tid < 256){                     // 16 tokens x 16 float4
            int rr = tid >> 4, seg = tid & 15;
            float4 v = x4[(ttile+rr)*16 + seg];
            *(float4*)&xs[rr*64 + ((seg*4) ^ ((rr&3)*8))] = v;
        }
        __syncthreads();

        u64 acc[4][2];
        #pragma unroll
        for(int i=0;i<4;i++){ acc[i][0]=0; acc[i][1]=0; }

        #pragma unroll 2
        for(int k4=0;k4<16;k4++){
            float v4[4][4];
            #pragma unroll
            for(int i=0;i<4;i++)
                *(float4*)v4[i] = *(const float4*)&xs[(tg+4*i)*64 + ((k4*4) ^ xsw)];
            #pragma unroll
            for(int kk=0;kk<4;kk++){
                int k = k4*4 + kk;
                ulonglong2 p0 = *(const ulonglong2*)&g_ctrT[k*NC + cb];
                #pragma unroll
                for(int i=0;i<4;i++){
                    u64 xv = dupf(v4[i][kk]);
                    ffma2(acc[i][0], xv, p0.x);
                    ffma2(acc[i][1], xv, p0.y);
                }
            }
        }
        // key = c2b - 2*(x.c), write to ds
        {
            ulonglong2 q0 = *(const ulonglong2*)&g_c2[cb];
            u64 m2 = dupf(-2.0f);
            #pragma unroll
            for(int i=0;i<4;i++){
                int r = tg + 4*i;
                *(ulonglong2*)&ds[r*NC + cb] =
                    make_ulonglong2(ffma2v(acc[i][0], m2, q0.x),
                                    ffma2v(acc[i][1], m2, q0.y));
            }
        }
        __syncthreads();

        // selection + scatter: warp w handles token w (16 warps, 16 tokens)
        select16(ds, w, lane, ttile + w);
    }
}

// ---------------- K2: tile-list build (1 block, shuffle scan) -------------------
__global__ __launch_bounds__(512) void k_tiles(){
    __shared__ int wsum[16];
    int c = threadIdx.x, lane = c & 31, w = c >> 5;
    int t = (g_cnt[c] + 127) >> 7;
    int s = t;
    #pragma unroll
    for(int o=1;o<32;o<<=1){ int v=__shfl_up_sync(0xffffffffu,s,o); if(lane>=o) s+=v; }
    if(lane==31) wsum[w] = s;
    __syncthreads();
    if(w==0){
        int tt = (lane<16) ? wsum[lane] : 0;
        #pragma unroll
        for(int o=1;o<16;o<<=1){ int v=__shfl_up_sync(0xffffffffu,tt,o); if(lane>=o) tt+=v; }
        if(lane<16) wsum[lane] = tt;
    }
    __syncthreads();
    int tinc = s + ((w>0) ? wsum[w-1] : 0);
    int tb = tinc - t;
    for(int i=0;i<t;i++){
        g_tiles[2*(tb+i)]   = c;
        g_tiles[2*(tb+i)+1] = i << 7;
    }
    if(c == 511) g_ntiles = tinc;
}

// ---------------- K3: grouped GEMM per (center, 128-row tile) ------------------
// 256 thr, thread tile 4 rows x 8 cols (split og*4 / og*4+32).
// Warp w owns rows [16w, 16w+16): whole-warp skip when 16w >= m.
__global__ __launch_bounds__(256,3) void k_gemm(const float* __restrict__ x,
                                                const float* __restrict__ Wv,
                                                const float* __restrict__ Ov){
    __shared__ float ws[DIN*DOUT];   // ws[k*64 + p] (row-major copy of Wv[c])
    __shared__ float xs[128*DIN];    // xs[r*64 + (k ^ 8*((r>>2)&3))]
    __shared__ int s_tile;
    int nt = g_ntiles;
    int tid = threadIdx.x;
    int og = tid & 7, tg = tid >> 3;     // tg 0..31
    int w  = tid >> 5;
    int xsw = (tg & 3) * 8;              // rows tg*4..tg*4+3 share (r>>2)&3 == tg&3
    const float4* x4 = (const float4*)x;

    while(true){
        __syncthreads();             // smem reuse + s_tile protection
        if(tid == 0) s_tile = atomicAdd(&g_work, 1);
        __syncthreads();
        int tile = s_tile;
        if(tile >= nt) break;

        int c      = g_tiles[2*tile];
        int rstart = g_tiles[2*tile+1];
        size_t base = (size_t)c*CAP + rstart;
        int m      = g_cnt[c] - rstart; if(m > 128) m = 128;

        const float4* wv4 = (const float4*)(Wv + (size_t)c*4096);
        float4* ws4 = (float4*)ws;
        #pragma unroll
        for(int f=0; f<4; f++) ws4[tid + 256*f] = wv4[tid + 256*f];

        #pragma unroll
        for(int it=0; it<8; it++){
            int idx2 = tid + 256*it;
            int rr = idx2 >> 4, seg = idx2 & 15;
            if(rr < m){
                float4 v = x4[g_tok[base+rr]*16 + seg];
                *(float4*)&xs[rr*64 + ((seg*4) ^ (((rr>>2)&3)*8))] = v;
            }
        }
        __syncthreads();

        if(16*w < m){                   // warp-uniform: skip padded rows
            u64 acc[4][4];
            #pragma unroll
            for(int i=0;i<4;i++){ acc[i][0]=0; acc[i][1]=0; acc[i][2]=0; acc[i][3]=0; }

            #pragma unroll 4
            for(int k4=0;k4<16;k4++){
                float v4[4][4];
                #pragma unroll
                for(int i=0;i<4;i++)
                    *(float4*)v4[i] = *(const float4*)&xs[(tg*4+i)*64 + ((k4*4) ^ xsw)];
                #pragma unroll
                for(int kk=0;kk<4;kk++){
                    int k = k4*4 + kk;
                    ulonglong2 p0 = *(const ulonglong2*)&ws[k*64 + og*4];
                    ulonglong2 p1 = *(const ulonglong2*)&ws[k*64 + og*4 + 32];
                    #pragma unroll
                    for(int i=0;i<4;i++){
                        u64 xv = dupf(v4[i][kk]);
                        ffma2(acc[i][0], xv, p0.x);
                        ffma2(acc[i][1], xv, p0.y);
                        ffma2(acc[i][2], xv, p1.x);
                        ffma2(acc[i][3], xv, p1.y);
                    }
                }
            }
            ulonglong2 q0 = *(const ulonglong2*)&Ov[(size_t)c*64 + og*4];
            ulonglong2 q1 = *(const ulonglong2*)&Ov[(size_t)c*64 + og*4 + 32];
            #pragma unroll
            for(int i=0;i<4;i++){
                int r = tg*4 + i;
                if(r < m){
                    int slot = g_dslot[base + r];
                    u64 sv = dupf(g_ascore[base + r]);
                    ulonglong2* d0 = (ulonglong2*)&g_part[(size_t)slot*64 + og*4];
                    ulonglong2* d1 = (ulonglong2*)&g_part[(size_t)slot*64 + og*4 + 32];
                    *d0 = make_ulonglong2(fmul2(fadd2(acc[i][0], q0.x), sv),
                                          fmul2(fadd2(acc[i][1], q0.y), sv));
                    *d1 = make_ulonglong2(fmul2(fadd2(acc[i][2], q1.x), sv),
                                          fmul2(fadd2(acc[i][3], q1.y), sv));
                }
            }
        }
    }
}

// ---------------- K4: streamed reduce of 16 contiguous partials per token ------
__global__ __launch_bounds__(256) void k_reduce(float* __restrict__ out){
    int t  = blockIdx.x*16 + (threadIdx.x >> 4);
    int c4 = threadIdx.x & 15;
    const float4* p = (const float4*)(g_part + (size_t)t*16*64) + c4;
    float4 acc = make_float4(0.f,0.f,0.f,0.f);
    #pragma unroll
    for(int j=0;j<16;j++){
        float4 v = p[j*16];
        acc.x += v.x; acc.y += v.y; acc.z += v.z; acc.w += v.w;
    }
    ((float4*)out)[t*16 + c4] = acc;
}

// ---------------- launch -------------------------------------------------------
extern "C" void kernel_launch(void* const* d_in, const int* in_sizes, int n_in,
                              void* d_out, int out_size){
    const float* x    = (const float*)d_in[0];
    const float* ctrs = (const float*)d_in[1];
    const float* Wv   = (const float*)d_in[2];
    const float* Ov   = (const float*)d_in[3];
    float* out = (float*)d_out;

    const int FUSED_SMEM = (16*64 + 16*NC)*4;   // 36 KB
    cudaFuncSetAttribute(k_fused, cudaFuncAttributeMaxDynamicSharedMemorySize,
                         FUSED_SMEM);

    k_prep_t <<<128, 256>>>(ctrs);
    k_prep_cz<<<2, 256>>>(ctrs);
    k_fused  <<<148, 512, FUSED_SMEM>>>(x);
    k_tiles  <<<1, 512>>>();            // launch #4 -> ncu capture target
    k_gemm   <<<444, 256>>>(x, Wv, Ov);
    k_reduce <<<1024, 256>>>(out);
}